// round 11
// baseline (speedup 1.0000x reference)
#include <cuda_runtime.h>
#include <cuda_fp16.h>
#include <math.h>
#include <stdint.h>

#define BATCH   32
#define SEQ     4096
#define C_IN    7
#define NF      35
#define D_MODEL 512
#define WINDOW  24
#define KDIM    105
#define LDH     120          // halfs per A/W row (240B)
// A row layout: [F[s-1] @0..35 | F[s] @36..71 | F[s+1] @72..107], pad 108..119.
// F row = 36 halfs (col 35 = 0).  W col = tap*36 + i, zero at gaps.

// Compact fp16 feature rows: [BATCH*SEQ][36]
__device__ __align__(16) __half g_F[(size_t)BATCH * SEQ * 36];
// W reordered/padded fp16: [D_MODEL][LDH]
__device__ __align__(16) __half g_Wh[D_MODEL * LDH];

// ---------------------------------------------------------------------------
// Phase 1 (fused): rolling stats -> g_F;  W prep on the extra y-slice.
// ---------------------------------------------------------------------------
#define P1_TS 256
#define WPREP_BLOCKS ((D_MODEL * LDH) / P1_TS)   // 240
#define FST 19                                   // staging row stride in u32 (38 halfs)

__global__ __launch_bounds__(P1_TS) void stats_kernel(const float* __restrict__ x,
                                                      const float* __restrict__ Wg) {
    const int tid = threadIdx.x;

    if (blockIdx.y == BATCH) {
        // W prep: col = tap*36 + i  ->  W[n][i*3 + tap]; gaps zero
        int idx = blockIdx.x * P1_TS + tid;
        int n = idx / LDH, k = idx - n * LDH;
        int tap = k / 36, i = k - tap * 36;
        float v = 0.0f;
        if (k < 108 && i < NF) v = Wg[(size_t)n * KDIM + i * 3 + tap];
        g_Wh[idx] = __float2half(v);
        return;
    }
    if (blockIdx.x >= SEQ / P1_TS) return;

    __shared__ uint32_t fst[P1_TS * FST];                    // 19456 B
    __shared__ float sx[(P1_TS + WINDOW - 1) * C_IN];        //  7812 B

    const int b   = blockIdx.y;
    const int s0  = blockIdx.x * P1_TS;
    const float* xb = x + (size_t)b * SEQ * C_IN;

    for (int idx = tid; idx < (P1_TS + WINDOW - 1) * C_IN; idx += P1_TS) {
        int sg = s0 - (WINDOW - 1) + idx / C_IN;
        int c  = idx % C_IN;
        if (sg < 0) sg = 0;
        sx[idx] = xb[(size_t)sg * C_IN + c];
    }
    __syncthreads();

    float f[NF];
    #pragma unroll
    for (int c = 0; c < C_IN; c++) {
        float sum = 0.0f, mx = -3.0e38f, mn = 3.0e38f;
        #pragma unroll
        for (int t = 0; t < WINDOW; t++) {
            float v = sx[(tid + t) * C_IN + c];
            sum += v; mx = fmaxf(mx, v); mn = fminf(mn, v);
        }
        float mean = sum * (1.0f / WINDOW);
        float s2 = 0.0f;
        #pragma unroll
        for (int t = 0; t < WINDOW; t++) {
            float d = sx[(tid + t) * C_IN + c] - mean;
            s2 += d * d;
        }
        f[c]      = sx[(tid + WINDOW - 1) * C_IN + c];
        f[7 + c]  = mean;
        f[14 + c] = mx;
        f[21 + c] = mn;
        f[28 + c] = sqrtf(s2 * (1.0f / (WINDOW - 1)) + 1e-12f);
    }

    // pack & stage own row (stride 19 u32, coprime with 32 -> conflict-free)
    uint32_t* my = fst + tid * FST;
    #pragma unroll
    for (int i = 0; i < 17; i++) {
        __half2 h = __floats2half2_rn(f[2 * i], f[2 * i + 1]);
        my[i] = *(uint32_t*)&h;
    }
    {
        __half h = __float2half(f[34]);
        my[17] = (uint32_t)*(uint16_t*)&h;     // col 35 = 0
    }
    __syncthreads();

    // coalesced write: 256 rows x 18 u32 contiguous
    uint32_t* dst = (uint32_t*)g_F + ((size_t)b * SEQ + s0) * 18;
    for (int idx = tid; idx < P1_TS * 18; idx += P1_TS) {
        int r = idx / 18, c = idx - r * 18;
        dst[idx] = fst[r * FST + c];
    }
}

// ---------------------------------------------------------------------------
// Phase 2: fp16 mma.sync GEMM, full fp16 accumulation chain.
// CTA 64(M) x 128(N), 8 warps (2M x 4N), warp 32x32, 4 CTAs/SM.
// A built from 3 overlapping slices of compact g_F; staged f16 epilogue.
// ---------------------------------------------------------------------------
#define BM 64
#define BN 128
#define CTH 256
#define SMEMB (BM * LDH * 2 + BN * LDH * 2 + BN * 4)   // 46592 bytes
#define EST 68    // epilogue stage row stride (u32)

__device__ __forceinline__ uint32_t smem_u32(const void* p) {
    uint32_t a;
    asm("{ .reg .u64 t; cvta.to.shared.u64 t, %1; cvt.u32.u64 %0, t; }" : "=r"(a) : "l"(p));
    return a;
}

__global__ __launch_bounds__(CTH, 4) void mma_kernel(const float* __restrict__ bias,
                                                     float* __restrict__ out) {
    extern __shared__ char smem[];
    __half* sA    = (__half*)smem;                       // [BM][LDH]
    __half* sB    = (__half*)(smem + BM * LDH * 2);      // [BN][LDH]
    float*  sBias = (float*)(smem + (BM + BN) * LDH * 2);
    uint32_t* stage = (uint32_t*)smem;                   // reused post-mainloop

    const int tid = threadIdx.x;
    const int mt  = blockIdx.x;               // 2048 M-tiles
    const int b   = mt >> 6;
    const int s0  = (mt & 63) * BM;
    const int n0  = blockIdx.y * BN;

    // ---- A: 3 overlapping slices of g_F (u32 units; 60 u32 per sA row) ----
    {
        const uint32_t* Fu = (const uint32_t*)g_F + (size_t)b * SEQ * 18;
        uint32_t* dst = (uint32_t*)sA;
        for (int idx = tid; idx < BM * 60; idx += CTH) {
            int r = idx / 60, c = idx - r * 60;
            uint32_t v = 0;
            if (c < 54) {
                int sl = (c >= 36) ? 2 : ((c >= 18) ? 1 : 0);
                int cc = c - sl * 18;
                int ss = (s0 + r - 1 + sl) & (SEQ - 1);
                v = Fu[ss * 18 + cc];
            }
            dst[idx] = v;
        }
    }
    // ---- B: contiguous uint4 copy of W tile ----
    {
        const uint4* src = (const uint4*)(g_Wh + (size_t)n0 * LDH);
        uint4* dst = (uint4*)sB;
        for (int i = tid; i < BN * LDH * 2 / 16; i += CTH) dst[i] = src[i];
    }
    if (tid < BN) sBias[tid] = bias[n0 + tid];
    __syncthreads();

    const int lane = tid & 31, w = tid >> 5;
    const int g = lane >> 2, q = lane & 3;
    const int mw = (w & 1) * 32;              // 2 warps along M
    const int nw = (w >> 1) * 32;             // 4 warps along N

    const uint32_t saBase = smem_u32(sA);
    const uint32_t sbBase = smem_u32(sB);
    const uint32_t aAddr = saBase +
        2u * ((uint32_t)(mw + (lane & 15)) * LDH + ((lane >> 4) << 3));
    const uint32_t bt = lane >> 3, bj = lane & 7;
    const uint32_t bAddr = sbBase +
        2u * ((uint32_t)(nw + ((bt >> 1) << 3) + bj) * LDH + ((bt & 1) << 3));

    uint32_t d[2][4][2];
    #pragma unroll
    for (int mi = 0; mi < 2; mi++)
        #pragma unroll
        for (int ni = 0; ni < 4; ni++)
            d[mi][ni][0] = d[mi][ni][1] = 0u;

    #pragma unroll
    for (int ks = 0; ks < 7; ks++) {
        const uint32_t kOff = (uint32_t)ks * 32;   // bytes

        uint32_t bf[4][2];
        #pragma unroll
        for (int nset = 0; nset < 2; nset++) {
            uint32_t ba = bAddr + kOff + (uint32_t)(nset * 16 * LDH * 2);
            asm volatile(
                "ldmatrix.sync.aligned.m8n8.x4.shared.b16 {%0,%1,%2,%3}, [%4];"
                : "=r"(bf[2 * nset][0]),     "=r"(bf[2 * nset][1]),
                  "=r"(bf[2 * nset + 1][0]), "=r"(bf[2 * nset + 1][1])
                : "r"(ba));
        }

        #pragma unroll
        for (int mi = 0; mi < 2; mi++) {
            uint32_t af[4];
            uint32_t aa = aAddr + (uint32_t)(2 * (mi * 16 * LDH)) + kOff;
            asm volatile(
                "ldmatrix.sync.aligned.m8n8.x4.shared.b16 {%0,%1,%2,%3}, [%4];"
                : "=r"(af[0]), "=r"(af[1]), "=r"(af[2]), "=r"(af[3]) : "r"(aa));
            #pragma unroll
            for (int ni = 0; ni < 4; ni++)
                asm volatile(
                    "mma.sync.aligned.m16n8k16.row.col.f16.f16.f16.f16 "
                    "{%0,%1}, {%2,%3,%4,%5}, {%6,%7}, {%0,%1};"
                    : "+r"(d[mi][ni][0]), "+r"(d[mi][ni][1])
                    : "r"(af[0]), "r"(af[1]), "r"(af[2]), "r"(af[3]),
                      "r"(bf[ni][0]), "r"(bf[ni][1]));
        }
    }

    // ---- epilogue: stage f16 accumulators -> coalesced f32 stores ----
    float4 bv = *(const float4*)&sBias[lane * 4];   // cols lane*4 .. +3
    __syncthreads();                                // all LDSM done; reuse sA/sB

    // STS: addr = row*EST + colu;  per-instr lanes: 4g+q mod 32 -> conflict-free
    #pragma unroll
    for (int mi = 0; mi < 2; mi++)
        #pragma unroll
        for (int ni = 0; ni < 4; ni++) {
            uint32_t colu = (uint32_t)(nw / 2 + ni * 4 + q);
            uint32_t r0 = (uint32_t)(mw + mi * 16 + g);
            stage[r0 * EST + colu]       = d[mi][ni][0];
            stage[(r0 + 8) * EST + colu] = d[mi][ni][1];
        }
    __syncthreads();

    // 8 passes: warp w writes row p*8+w; lane covers 4 consecutive cols
    float* obase = out + ((size_t)mt * BM) * D_MODEL + n0 + lane * 4;
    #pragma unroll
    for (int p = 0; p < 8; p++) {
        int row = p * 8 + w;
        uint2 pk = *(const uint2*)&stage[row * EST + lane * 2];
        float2 lo = __half22float2(*(__half2*)&pk.x);
        float2 hi = __half22float2(*(__half2*)&pk.y);
        float4 v = { lo.x + bv.x, lo.y + bv.y, hi.x + bv.z, hi.y + bv.w };
        *(float4*)(obase + (size_t)row * D_MODEL) = v;
    }
}

// ---------------------------------------------------------------------------
extern "C" void kernel_launch(void* const* d_in, const int* in_sizes, int n_in,
                              void* d_out, int out_size) {
    const float* x = nullptr; const float* Wg = nullptr; const float* bias = nullptr;
    for (int i = 0; i < n_in; i++) {
        if (in_sizes[i] == BATCH * SEQ * C_IN)   x    = (const float*)d_in[i];
        else if (in_sizes[i] == D_MODEL * KDIM)  Wg   = (const float*)d_in[i];
        else if (in_sizes[i] == D_MODEL)         bias = (const float*)d_in[i];
        // x_mark (BATCH*SEQ*4) unused by the reference math
    }
    float* out = (float*)d_out;

    dim3 g1(WPREP_BLOCKS, BATCH + 1);
    stats_kernel<<<g1, P1_TS>>>(x, Wg);

    cudaFuncSetAttribute(mma_kernel, cudaFuncAttributeMaxDynamicSharedMemorySize, SMEMB);
    dim3 g2((BATCH * SEQ) / BM, D_MODEL / BN, 1);
    mma_kernel<<<g2, CTH, SMEMB>>>(bias, out);
}